// round 9
// baseline (speedup 1.0000x reference)
#include <cuda_runtime.h>
#include <cstdint>

#define Bg   16
#define Nn   128
#define Mm   (Bg * Nn)     // 2048 nodes
#define Dd   256
#define TRI  ((Dd * (Dd + 1)) / 2)   // 32896
#define TRI4 (TRI / 4)               // 8224

__device__ float g_s[Mm];   // per-node softmax weight

// ---------------------------------------------------------------------------
// K1: fused linear (D->1) + segment softmax. One block per graph.
// ---------------------------------------------------------------------------
__global__ __launch_bounds__(1024) void k_attn_softmax(
    const float* __restrict__ x, const float* __restrict__ W,
    const float* __restrict__ b)
{
    int g    = blockIdx.x;
    int tid  = threadIdx.x;
    int warp = tid >> 5;
    int lane = tid & 31;

    __shared__ float simp[Nn];
    __shared__ float red[2];

    float wv[8];
#pragma unroll
    for (int u = 0; u < 8; u++) wv[u] = __ldg(&W[lane + 32 * u]);

#pragma unroll
    for (int nn = 0; nn < 4; nn++) {
        int node = warp * 4 + nn;
        const float* xr = x + (size_t)(g * Nn + node) * Dd;
        float acc = 0.f;
#pragma unroll
        for (int u = 0; u < 8; u++) acc = fmaf(xr[lane + 32 * u], wv[u], acc);
#pragma unroll
        for (int o = 16; o; o >>= 1) acc += __shfl_xor_sync(0xffffffffu, acc, o);
        if (lane == 0) simp[node] = acc + b[0];
    }
    __syncthreads();

    if (warp == 0) {
        float v0 = simp[lane], v1 = simp[lane + 32],
              v2 = simp[lane + 64], v3 = simp[lane + 96];
        float mx = fmaxf(fmaxf(v0, v1), fmaxf(v2, v3));
#pragma unroll
        for (int o = 16; o; o >>= 1) mx = fmaxf(mx, __shfl_xor_sync(0xffffffffu, mx, o));
        float sum = expf(v0 - mx) + expf(v1 - mx) + expf(v2 - mx) + expf(v3 - mx);
#pragma unroll
        for (int o = 16; o; o >>= 1) sum += __shfl_xor_sync(0xffffffffu, sum, o);
        if (lane == 0) { red[0] = mx; red[1] = sum; }
    }
    __syncthreads();

    if (tid < Nn)
        g_s[g * Nn + tid] = expf(simp[tid] - red[0]) * (1.0f / red[1]);
}

// ---------------------------------------------------------------------------
// K2: row-structured triu outer-product stream. One block per node.
// Warp handles row pair (p, 255-p): combined length ~257 -> balanced.
// Row i owns float4 groups [rs(i)>>2, rs(i+1)>>2)  (telescoping, exact cover).
// Interior body: LDS.128 + 4 FMUL + STG.128 (y[i] uniform in a register).
// Row-head groups straddling the previous row are rewritten exactly by lane 0.
// ---------------------------------------------------------------------------
__global__ __launch_bounds__(256) void k_sop(
    const float* __restrict__ x, float* __restrict__ out)
{
    int m    = blockIdx.x;
    int tid  = threadIdx.x;
    int warp = tid >> 5;
    int lane = tid & 31;

    __shared__ float  yp[276];       // ypad: [0..3]=0, [4+i]=y_i, [260..275]=0
    __shared__ float4 z[4 * 68];     // phase images: z[c*68+q] = yp[4q+c .. +3]

    float s = __ldg(&g_s[m]);
    yp[4 + tid] = x[(size_t)m * Dd + tid] * s;
    if (tid < 4)  yp[tid] = 0.0f;
    if (tid < 16) yp[260 + tid] = 0.0f;
    __syncthreads();

    for (int idx = tid; idx < 272; idx += 256) {
        int c = idx / 68;
        int q = idx - c * 68;
        int b = 4 * q + c;           // max 271 -> reads yp[274], in bounds
        z[idx] = make_float4(yp[b], yp[b + 1], yp[b + 2], yp[b + 3]);
    }
    __syncthreads();

    float4* __restrict__ out4 = (float4*)(out + (size_t)m * TRI);

    for (int p = warp; p < 128; p += 8) {
#pragma unroll
        for (int side = 0; side < 2; side++) {
            int i = side ? (255 - p) : p;

            int rs   = (i * (513 - i)) >> 1;            // row start
            int rs1  = ((i + 1) * (512 - i)) >> 1;      // next row start
            int gbeg = rs  >> 2;
            int gend = rs1 >> 2;
            int n    = gend - gbeg;
            if (n <= 0) continue;                        // row 254 owns nothing

            float yi    = yp[4 + i];
            int   jpad0 = 4 * gbeg - rs + i + 4;         // >= 1 always
            int   zrow  = (jpad0 & 3) * 68 + (jpad0 >> 2);

            for (int t = lane; t < n; t += 32) {
                float4 w = z[zrow + t];
                __stcs(&out4[gbeg + t],
                       make_float4(yi * w.x, yi * w.y, yi * w.z, yi * w.w));
            }

            int sh = rs & 3;                             // head elems from prev row
            if (lane == 0 && sh) {
                float4 r;
                if (i == 255) {                          // 3-row group 8223
                    float a = yp[4 + 253], bb = yp[4 + 254], c = yp[4 + 255];
                    r = make_float4(a * c, bb * bb, bb * c, c * c);
                } else {
                    int   rsp   = ((i - 1) * (514 - i)) >> 1;   // row_start(i-1)
                    float yprev = yp[4 + i - 1];
                    int   k0    = 4 * gbeg;
                    float v[4];
#pragma unroll
                    for (int e = 0; e < 4; e++) {
                        int k = k0 + e;
                        v[e] = (k < rs)
                             ? yprev * yp[4 + (k - rsp + i - 1)]
                             : yi    * yp[4 + (k - rs  + i)];
                    }
                    r = make_float4(v[0], v[1], v[2], v[3]);
                }
                __stcs(&out4[gbeg], r);   // same thread as t=0 store: ordered
            }
        }
    }
}

// ---------------------------------------------------------------------------
extern "C" void kernel_launch(void* const* d_in, const int* in_sizes, int n_in,
                              void* d_out, int out_size)
{
    const float* x = (const float*)d_in[0];
    const float* W = (const float*)d_in[3];
    const float* b = (const float*)d_in[4];
    float* out = (float*)d_out;

    k_attn_softmax<<<Bg, 1024>>>(x, W, b);
    k_sop<<<Mm, 256>>>(x, out);
}

// round 14
// speedup vs baseline: 1.4577x; 1.4577x over previous
#include <cuda_runtime.h>
#include <cstdint>

#define Bg   16
#define Nn   128
#define Mm   (Bg * Nn)     // 2048 nodes
#define Dd   256
#define TRI  ((Dd * (Dd + 1)) / 2)   // 32896
#define TRI4 (TRI / 4)               // 8224

__device__ float         g_s[Mm];       // per-node softmax weight
__device__ unsigned char g_itab[TRI4];  // per-group first-row index i0

__device__ __forceinline__ int row_start(int i) { return (i * (513 - i)) >> 1; }

__device__ __forceinline__ int row_of(int t) {
    int i = (int)(0.5f * (513.0f - sqrtf((float)(263169 - 8 * t))));
    if (row_start(i + 1) <= t) i++;
    if (row_start(i) > t)      i--;
    return i;
}

// ---------------------------------------------------------------------------
// K1: fused (a) linear D->1 + segment softmax  (b) per-group i0 table build.
// One block per graph, 1024 threads (16*1024 >= TRI4).
// ---------------------------------------------------------------------------
__global__ __launch_bounds__(1024) void k_attn_softmax(
    const float* __restrict__ x, const float* __restrict__ W,
    const float* __restrict__ b)
{
    int g    = blockIdx.x;
    int tid  = threadIdx.x;
    int warp = tid >> 5;
    int lane = tid & 31;

    __shared__ float simp[Nn];
    __shared__ float red[2];

    {   // table: i0 of each float4 group
        int k4 = g * 1024 + tid;
        if (k4 < TRI4) g_itab[k4] = (unsigned char)row_of(4 * k4);
    }

    float wv[8];
#pragma unroll
    for (int u = 0; u < 8; u++) wv[u] = __ldg(&W[lane + 32 * u]);

#pragma unroll
    for (int nn = 0; nn < 4; nn++) {
        int node = warp * 4 + nn;
        const float* xr = x + (size_t)(g * Nn + node) * Dd;
        float acc = 0.f;
#pragma unroll
        for (int u = 0; u < 8; u++) acc = fmaf(xr[lane + 32 * u], wv[u], acc);
#pragma unroll
        for (int o = 16; o; o >>= 1) acc += __shfl_xor_sync(0xffffffffu, acc, o);
        if (lane == 0) simp[node] = acc + b[0];
    }
    __syncthreads();

    if (warp == 0) {
        float v0 = simp[lane], v1 = simp[lane + 32],
              v2 = simp[lane + 64], v3 = simp[lane + 96];
        float mx = fmaxf(fmaxf(v0, v1), fmaxf(v2, v3));
#pragma unroll
        for (int o = 16; o; o >>= 1) mx = fmaxf(mx, __shfl_xor_sync(0xffffffffu, mx, o));
        float sum = expf(v0 - mx) + expf(v1 - mx) + expf(v2 - mx) + expf(v3 - mx);
#pragma unroll
        for (int o = 16; o; o >>= 1) sum += __shfl_xor_sync(0xffffffffu, sum, o);
        if (lane == 0) { red[0] = mx; red[1] = sum; }
    }
    __syncthreads();

    if (tid < Nn)
        g_s[g * Nn + tid] = expf(simp[tid] - red[0]) * (1.0f / red[1]);
}

// ---------------------------------------------------------------------------
// K2: flat triu stream, branchless two-run groups. One block per node.
// Every group spans <=2 rows (sole exception: last group, fixed by one
// predicated FMUL). From smem u8 i0: derive rs, split, both z windows;
// resolve 4 elements with FSELs. Dense STG.128, no divergence, no holes.
// ---------------------------------------------------------------------------
__global__ __launch_bounds__(256) void k_sop(
    const float* __restrict__ x, float* __restrict__ out)
{
    int m   = blockIdx.x;
    int tid = threadIdx.x;

    __shared__ float         yp[276];      // [0..3]=0, [4+i]=y_i, [260..275]=0
    __shared__ float4        z[4 * 68];    // phase images: z[c*68+q]=yp[4q+c..+3]
    __shared__ unsigned char itab[TRI4];   // per-group i0

    float s = __ldg(&g_s[m]);
    yp[4 + tid] = x[(size_t)m * Dd + tid] * s;
    if (tid < 4)  yp[tid] = 0.0f;
    if (tid < 16) yp[260 + tid] = 0.0f;
    __syncthreads();

    {   // phase images (reads yp) + table copy (independent)
        int c = tid >> 6;              // 0..3
        int q = tid & 63;              // 0..63
        int b4 = 4 * q + c;
        z[c * 68 + q] = make_float4(yp[b4], yp[b4 + 1], yp[b4 + 2], yp[b4 + 3]);
        if (tid < 16) {                // extra z entries q=64..67 per phase
            int cc = tid >> 2, qq = 64 + (tid & 3);
            int bb = 4 * qq + cc;      // max 271 -> reads yp[274], in bounds
            z[cc * 68 + qq] = make_float4(yp[bb], yp[bb + 1], yp[bb + 2], yp[bb + 3]);
        }
        const uint32_t* src = (const uint32_t*)g_itab;
        uint32_t*       dst = (uint32_t*)itab;
        for (int idx = tid; idx < TRI4 / 4; idx += 256) dst[idx] = src[idx];
    }
    __syncthreads();

    float4* __restrict__ out4 = (float4*)(out + (size_t)m * TRI);

    for (int k4 = tid; k4 < TRI4; k4 += 256) {
        int i0  = (int)itab[k4];
        int rs  = (i0 * (513 - i0)) >> 1;
        int k   = 4 * k4;
        int jp0 = k - rs + i0 + 4;                     // padded j of elem 0
        float4 w0 = z[(jp0 & 3) * 68 + (jp0 >> 2)];    // y[j0 .. j0+3]
        int jp1 = i0 + 5;                              // padded j at next row diag
        float4 w1 = z[(jp1 & 3) * 68 + (jp1 >> 2)];    // y[i0+1 .. i0+4]
        float yi0 = yp[4 + i0];
        float yi1 = yp[5 + i0];
        int split = rs + 256 - i0 - k;                 // rs(i0+1) - k; >=1

        float ys1 = (split > 1) ? yi0 : yi1;
        float ys2 = (split > 2) ? yi0 : yi1;
        float ys3 = (split > 3) ? yi0 : yi1;
        float w_1 = (split > 1) ? w0.y : w1.x;
        float w_2 = (split > 2) ? w0.z : ((split == 2) ? w1.x : w1.y);
        float w_3 = (split > 3) ? w0.w
                  : ((split == 3) ? w1.x : ((split == 2) ? w1.y : w1.z));

        float4 r = make_float4(yi0 * w0.x, ys1 * w_1, ys2 * w_2, ys3 * w_3);
        if (k4 == TRI4 - 1) r.w = w1.y * w1.y;         // lone 3-row tail group
        __stcs(&out4[k4], r);
    }
}

// ---------------------------------------------------------------------------
extern "C" void kernel_launch(void* const* d_in, const int* in_sizes, int n_in,
                              void* d_out, int out_size)
{
    const float* x = (const float*)d_in[0];
    const float* W = (const float*)d_in[3];
    const float* b = (const float*)d_in[4];
    float* out = (float*)d_out;

    k_attn_softmax<<<Bg, 1024>>>(x, W, b);
    k_sop<<<Mm, 256>>>(x, out);
}